// round 1
// baseline (speedup 1.0000x reference)
#include <cuda_runtime.h>

// NTN: out[n,k] = relu( cos(x1@W1[k], x2@W2[k]) + [x1,x2]@V[k] + b[k] )
// N=32768, D=128, K=32. fp32 exact path (CUDA cores), round-0 baseline.

#define NN   32768
#define DD   128
#define KK   32
#define BM   128      // rows per CTA
#define EB   64       // e-columns per block (2 blocks cover D)
#define RS   130      // X smem row stride (floats): 4*RS % 32 == 8 -> conflict-free a-frags
#define WS   68       // W smem row stride (floats): float4-aligned, conflict-free b-frags
#define EPSN 1e-8f

#define SMEM_FLOATS (2*BM*RS + 2*DD*WS + 2*DD)
#define SMEM_BYTES  (SMEM_FLOATS * 4)

__global__ __launch_bounds__(256, 1)
void ntn_fp32_kernel(const float* __restrict__ x1g_,
                     const float* __restrict__ x2g_,
                     const float* __restrict__ W1g,
                     const float* __restrict__ W2g,
                     const float* __restrict__ Vg,
                     const float* __restrict__ bg,
                     float* __restrict__ out) {
    extern __shared__ float smem[];
    float* X1s = smem;                 // [BM][RS]
    float* X2s = X1s + BM * RS;        // [BM][RS]
    float* W1s = X2s + BM * RS;        // [DD][WS]
    float* W2s = W1s + DD * WS;        // [DD][WS]
    float* Vs  = W2s + DD * WS;        // [2*DD]

    const int tid   = threadIdx.x;
    const int k     = blockIdx.y;
    const int rbase = blockIdx.x * BM;

    // ---- load X tiles (natural [row][d] layout, stride RS) ----
    const float* x1g = x1g_ + (size_t)rbase * DD;
    const float* x2g = x2g_ + (size_t)rbase * DD;
    #pragma unroll
    for (int i = 0; i < 16; i++) {
        int li   = tid + 256 * i;
        int row  = li >> 5;     // 0..127
        int dblk = li & 31;     // float4 index 0..31
        float4 v1 = ((const float4*)(x1g + row * DD))[dblk];
        float4 v2 = ((const float4*)(x2g + row * DD))[dblk];
        float* p1 = X1s + row * RS + dblk * 4;
        float* p2 = X2s + row * RS + dblk * 4;
        // stride 130 is float2-aligned but not float4-aligned -> 2x float2 stores
        ((float2*)p1)[0] = make_float2(v1.x, v1.y);
        ((float2*)p1)[1] = make_float2(v1.z, v1.w);
        ((float2*)p2)[0] = make_float2(v2.x, v2.y);
        ((float2*)p2)[1] = make_float2(v2.z, v2.w);
    }
    // ---- load V[k] (256 floats) ----
    if (tid < 64) {
        ((float4*)Vs)[tid] = ((const float4*)(Vg + (size_t)k * 2 * DD))[tid];
    }

    const int tx = tid & 7;    // col group: cols {4tx..4tx+3} and {32+4tx..}
    const int ty = tid >> 3;   // row group: rows 4ty..4ty+3

    float dot_[4] = {0.f, 0.f, 0.f, 0.f};
    float n1_[4]  = {0.f, 0.f, 0.f, 0.f};
    float n2_[4]  = {0.f, 0.f, 0.f, 0.f};

    const float* w1g = W1g + (size_t)k * DD * DD;
    const float* w2g = W2g + (size_t)k * DD * DD;

    for (int eb = 0; eb < DD / EB; eb++) {
        __syncthreads();   // protect W tiles (and X/V on first iter)
        // ---- load W e-block [DD][EB] for both matrices ----
        #pragma unroll
        for (int i = 0; i < 8; i++) {
            int li = tid + 256 * i;
            int fr = li >> 4;        // d row 0..127
            int fc = li & 15;        // float4 col 0..15
            float4 wv1 = ((const float4*)(w1g + fr * DD + eb * EB))[fc];
            float4 wv2 = ((const float4*)(w2g + fr * DD + eb * EB))[fc];
            ((float4*)(W1s + fr * WS))[fc] = wv1;
            ((float4*)(W2s + fr * WS))[fc] = wv2;
        }
        __syncthreads();

        // ---- register-blocked GEMM fragment: 4 rows x 8 cols x 2 matrices ----
        float c1[4][8], c2[4][8];
        #pragma unroll
        for (int ri = 0; ri < 4; ri++)
            #pragma unroll
            for (int cc = 0; cc < 8; cc++) { c1[ri][cc] = 0.f; c2[ri][cc] = 0.f; }

        #pragma unroll 4
        for (int d = 0; d < DD; d++) {
            float a1[4], a2[4];
            #pragma unroll
            for (int ri = 0; ri < 4; ri++) {
                a1[ri] = X1s[(4 * ty + ri) * RS + d];
                a2[ri] = X2s[(4 * ty + ri) * RS + d];
            }
            float4 b1a = *(const float4*)(W1s + d * WS + 4 * tx);
            float4 b1b = *(const float4*)(W1s + d * WS + 32 + 4 * tx);
            float4 b2a = *(const float4*)(W2s + d * WS + 4 * tx);
            float4 b2b = *(const float4*)(W2s + d * WS + 32 + 4 * tx);
            #pragma unroll
            for (int ri = 0; ri < 4; ri++) {
                c1[ri][0] += a1[ri] * b1a.x;  c1[ri][1] += a1[ri] * b1a.y;
                c1[ri][2] += a1[ri] * b1a.z;  c1[ri][3] += a1[ri] * b1a.w;
                c1[ri][4] += a1[ri] * b1b.x;  c1[ri][5] += a1[ri] * b1b.y;
                c1[ri][6] += a1[ri] * b1b.z;  c1[ri][7] += a1[ri] * b1b.w;
                c2[ri][0] += a2[ri] * b2a.x;  c2[ri][1] += a2[ri] * b2a.y;
                c2[ri][2] += a2[ri] * b2a.z;  c2[ri][3] += a2[ri] * b2a.w;
                c2[ri][4] += a2[ri] * b2b.x;  c2[ri][5] += a2[ri] * b2b.y;
                c2[ri][6] += a2[ri] * b2b.z;  c2[ri][7] += a2[ri] * b2b.w;
            }
        }
        // ---- fold x1t/x2t fragment into per-row reductions ----
        #pragma unroll
        for (int ri = 0; ri < 4; ri++)
            #pragma unroll
            for (int cc = 0; cc < 8; cc++) {
                dot_[ri] += c1[ri][cc] * c2[ri][cc];
                n1_[ri]  += c1[ri][cc] * c1[ri][cc];
                n2_[ri]  += c2[ri][cc] * c2[ri][cc];
            }
    }

    // ---- part2: [x1,x2] @ V[k], strided over tx (conflict-free banks) ----
    float p2_[4] = {0.f, 0.f, 0.f, 0.f};
    #pragma unroll
    for (int j = 0; j < 16; j++) {
        int d = tx + 8 * j;
        float vd  = Vs[d];
        float vd2 = Vs[DD + d];
        #pragma unroll
        for (int ri = 0; ri < 4; ri++) {
            int r = 4 * ty + ri;
            p2_[ri] += X1s[r * RS + d] * vd + X2s[r * RS + d] * vd2;
        }
    }

    // ---- reduce across the 8 tx lanes (consecutive lanes in-warp) ----
    #pragma unroll
    for (int off = 4; off >= 1; off >>= 1) {
        #pragma unroll
        for (int ri = 0; ri < 4; ri++) {
            dot_[ri] += __shfl_xor_sync(0xffffffffu, dot_[ri], off);
            n1_[ri]  += __shfl_xor_sync(0xffffffffu, n1_[ri],  off);
            n2_[ri]  += __shfl_xor_sync(0xffffffffu, n2_[ri],  off);
            p2_[ri]  += __shfl_xor_sync(0xffffffffu, p2_[ri],  off);
        }
    }

    if (tx == 0) {
        float bk = bg[k];
        #pragma unroll
        for (int ri = 0; ri < 4; ri++) {
            int r = 4 * ty + ri;
            float nc1 = fmaxf(sqrtf(n1_[ri]), EPSN);
            float nc2 = fmaxf(sqrtf(n2_[ri]), EPSN);
            float val = dot_[ri] / (nc1 * nc2) + p2_[ri] + bk;
            out[(size_t)(rbase + r) * KK + k] = fmaxf(val, 0.f);
        }
    }
}

extern "C" void kernel_launch(void* const* d_in, const int* in_sizes, int n_in,
                              void* d_out, int out_size) {
    const float* x1 = (const float*)d_in[0];
    const float* x2 = (const float*)d_in[1];
    const float* W1 = (const float*)d_in[2];
    const float* W2 = (const float*)d_in[3];
    const float* V  = (const float*)d_in[4];
    const float* b  = (const float*)d_in[5];
    float* out = (float*)d_out;

    cudaFuncSetAttribute(ntn_fp32_kernel,
                         cudaFuncAttributeMaxDynamicSharedMemorySize, SMEM_BYTES);
    dim3 grid(NN / BM, KK);
    ntn_fp32_kernel<<<grid, 256, SMEM_BYTES>>>(x1, x2, W1, W2, V, b, out);
}

// round 2
// speedup vs baseline: 1.0009x; 1.0009x over previous
#include <cuda_runtime.h>

// NTN: out[n,k] = relu( cos(x1@W1[k], x2@W2[k]) + [x1,x2]@V[k] + b[k] )
// N=32768, D=128, K=32. fp32 exact path (CUDA cores), round-0 baseline.

#define NN   32768
#define DD   128
#define KK   32
#define BM   128      // rows per CTA
#define EB   64       // e-columns per block (2 blocks cover D)
#define RS   130      // X smem row stride (floats): 4*RS % 32 == 8 -> conflict-free a-frags
#define WS   68       // W smem row stride (floats): float4-aligned, conflict-free b-frags
#define EPSN 1e-8f

#define SMEM_FLOATS (2*BM*RS + 2*DD*WS + 2*DD)
#define SMEM_BYTES  (SMEM_FLOATS * 4)

__global__ __launch_bounds__(256, 1)
void ntn_fp32_kernel(const float* __restrict__ x1g_,
                     const float* __restrict__ x2g_,
                     const float* __restrict__ W1g,
                     const float* __restrict__ W2g,
                     const float* __restrict__ Vg,
                     const float* __restrict__ bg,
                     float* __restrict__ out) {
    extern __shared__ float smem[];
    float* X1s = smem;                 // [BM][RS]
    float* X2s = X1s + BM * RS;        // [BM][RS]
    float* W1s = X2s + BM * RS;        // [DD][WS]
    float* W2s = W1s + DD * WS;        // [DD][WS]
    float* Vs  = W2s + DD * WS;        // [2*DD]

    const int tid   = threadIdx.x;
    const int k     = blockIdx.y;
    const int rbase = blockIdx.x * BM;

    // ---- load X tiles (natural [row][d] layout, stride RS) ----
    const float* x1g = x1g_ + (size_t)rbase * DD;
    const float* x2g = x2g_ + (size_t)rbase * DD;
    #pragma unroll
    for (int i = 0; i < 16; i++) {
        int li   = tid + 256 * i;
        int row  = li >> 5;     // 0..127
        int dblk = li & 31;     // float4 index 0..31
        float4 v1 = ((const float4*)(x1g + row * DD))[dblk];
        float4 v2 = ((const float4*)(x2g + row * DD))[dblk];
        float* p1 = X1s + row * RS + dblk * 4;
        float* p2 = X2s + row * RS + dblk * 4;
        // stride 130 is float2-aligned but not float4-aligned -> 2x float2 stores
        ((float2*)p1)[0] = make_float2(v1.x, v1.y);
        ((float2*)p1)[1] = make_float2(v1.z, v1.w);
        ((float2*)p2)[0] = make_float2(v2.x, v2.y);
        ((float2*)p2)[1] = make_float2(v2.z, v2.w);
    }
    // ---- load V[k] (256 floats) ----
    if (tid < 64) {
        ((float4*)Vs)[tid] = ((const float4*)(Vg + (size_t)k * 2 * DD))[tid];
    }

    const int tx = tid & 7;    // col group: cols {4tx..4tx+3} and {32+4tx..}
    const int ty = tid >> 3;   // row group: rows 4ty..4ty+3

    float dot_[4] = {0.f, 0.f, 0.f, 0.f};
    float n1_[4]  = {0.f, 0.f, 0.f, 0.f};
    float n2_[4]  = {0.f, 0.f, 0.f, 0.f};

    const float* w1g = W1g + (size_t)k * DD * DD;
    const float* w2g = W2g + (size_t)k * DD * DD;

    for (int eb = 0; eb < DD / EB; eb++) {
        __syncthreads();   // protect W tiles (and X/V on first iter)
        // ---- load W e-block [DD][EB] for both matrices ----
        #pragma unroll
        for (int i = 0; i < 8; i++) {
            int li = tid + 256 * i;
            int fr = li >> 4;        // d row 0..127
            int fc = li & 15;        // float4 col 0..15
            float4 wv1 = ((const float4*)(w1g + fr * DD + eb * EB))[fc];
            float4 wv2 = ((const float4*)(w2g + fr * DD + eb * EB))[fc];
            ((float4*)(W1s + fr * WS))[fc] = wv1;
            ((float4*)(W2s + fr * WS))[fc] = wv2;
        }
        __syncthreads();

        // ---- register-blocked GEMM fragment: 4 rows x 8 cols x 2 matrices ----
        float c1[4][8], c2[4][8];
        #pragma unroll
        for (int ri = 0; ri < 4; ri++)
            #pragma unroll
            for (int cc = 0; cc < 8; cc++) { c1[ri][cc] = 0.f; c2[ri][cc] = 0.f; }

        #pragma unroll 4
        for (int d = 0; d < DD; d++) {
            float a1[4], a2[4];
            #pragma unroll
            for (int ri = 0; ri < 4; ri++) {
                a1[ri] = X1s[(4 * ty + ri) * RS + d];
                a2[ri] = X2s[(4 * ty + ri) * RS + d];
            }
            float4 b1a = *(const float4*)(W1s + d * WS + 4 * tx);
            float4 b1b = *(const float4*)(W1s + d * WS + 32 + 4 * tx);
            float4 b2a = *(const float4*)(W2s + d * WS + 4 * tx);
            float4 b2b = *(const float4*)(W2s + d * WS + 32 + 4 * tx);
            #pragma unroll
            for (int ri = 0; ri < 4; ri++) {
                c1[ri][0] += a1[ri] * b1a.x;  c1[ri][1] += a1[ri] * b1a.y;
                c1[ri][2] += a1[ri] * b1a.z;  c1[ri][3] += a1[ri] * b1a.w;
                c1[ri][4] += a1[ri] * b1b.x;  c1[ri][5] += a1[ri] * b1b.y;
                c1[ri][6] += a1[ri] * b1b.z;  c1[ri][7] += a1[ri] * b1b.w;
                c2[ri][0] += a2[ri] * b2a.x;  c2[ri][1] += a2[ri] * b2a.y;
                c2[ri][2] += a2[ri] * b2a.z;  c2[ri][3] += a2[ri] * b2a.w;
                c2[ri][4] += a2[ri] * b2b.x;  c2[ri][5] += a2[ri] * b2b.y;
                c2[ri][6] += a2[ri] * b2b.z;  c2[ri][7] += a2[ri] * b2b.w;
            }
        }
        // ---- fold x1t/x2t fragment into per-row reductions ----
        #pragma unroll
        for (int ri = 0; ri < 4; ri++)
            #pragma unroll
            for (int cc = 0; cc < 8; cc++) {
                dot_[ri] += c1[ri][cc] * c2[ri][cc];
                n1_[ri]  += c1[ri][cc] * c1[ri][cc];
                n2_[ri]  += c2[ri][cc] * c2[ri][cc];
            }
    }

    // ---- part2: [x1,x2] @ V[k], strided over tx (conflict-free banks) ----
    float p2_[4] = {0.f, 0.f, 0.f, 0.f};
    #pragma unroll
    for (int j = 0; j < 16; j++) {
        int d = tx + 8 * j;
        float vd  = Vs[d];
        float vd2 = Vs[DD + d];
        #pragma unroll
        for (int ri = 0; ri < 4; ri++) {
            int r = 4 * ty + ri;
            p2_[ri] += X1s[r * RS + d] * vd + X2s[r * RS + d] * vd2;
        }
    }

    // ---- reduce across the 8 tx lanes (consecutive lanes in-warp) ----
    #pragma unroll
    for (int off = 4; off >= 1; off >>= 1) {
        #pragma unroll
        for (int ri = 0; ri < 4; ri++) {
            dot_[ri] += __shfl_xor_sync(0xffffffffu, dot_[ri], off);
            n1_[ri]  += __shfl_xor_sync(0xffffffffu, n1_[ri],  off);
            n2_[ri]  += __shfl_xor_sync(0xffffffffu, n2_[ri],  off);
            p2_[ri]  += __shfl_xor_sync(0xffffffffu, p2_[ri],  off);
        }
    }

    if (tx == 0) {
        float bk = bg[k];
        #pragma unroll
        for (int ri = 0; ri < 4; ri++) {
            int r = 4 * ty + ri;
            float nc1 = fmaxf(sqrtf(n1_[ri]), EPSN);
            float nc2 = fmaxf(sqrtf(n2_[ri]), EPSN);
            float val = dot_[ri] / (nc1 * nc2) + p2_[ri] + bk;
            out[(size_t)(rbase + r) * KK + k] = fmaxf(val, 0.f);
        }
    }
}

extern "C" void kernel_launch(void* const* d_in, const int* in_sizes, int n_in,
                              void* d_out, int out_size) {
    const float* x1 = (const float*)d_in[0];
    const float* x2 = (const float*)d_in[1];
    const float* W1 = (const float*)d_in[2];
    const float* W2 = (const float*)d_in[3];
    const float* V  = (const float*)d_in[4];
    const float* b  = (const float*)d_in[5];
    float* out = (float*)d_out;

    cudaFuncSetAttribute(ntn_fp32_kernel,
                         cudaFuncAttributeMaxDynamicSharedMemorySize, SMEM_BYTES);
    dim3 grid(NN / BM, KK);
    ntn_fp32_kernel<<<grid, 256, SMEM_BYTES>>>(x1, x2, W1, W2, V, b, out);
}

// round 4
// speedup vs baseline: 1.6896x; 1.6881x over previous
#include <cuda_runtime.h>
#include <cuda_bf16.h>
#include <cstdint>

// NTN via classic tensor-core mma.sync (bf16 hi/lo split-3, fp32 accum).
// out[n,k] = relu( cos(x1@W1[k], x2@W2[k]) + [x1,x2]@V[k] + b[k] )
// N=32768, D=128, K=32. CTA = 128 rows x 1 k, 256 threads.

#define NN 32768
#define DD 128
#define KK 32
#define BM 128
#define EPSN 1e-8f

// bf16 smem planes: X pitch 136 el (272B), W pitch 72 el (144B) -> ldmatrix conflict-free
#define XROWB 272
#define WROWB 144
#define XPL (128 * XROWB)          // 34816
#define WPL (128 * WROWB)          // 18432
#define OFF_X1H 0
#define OFF_X1L (XPL)
#define OFF_X2H (2 * XPL)
#define OFF_X2L (3 * XPL)
#define OFF_W   (4 * XPL)          // 139264
#define OFF_W1H (OFF_W)
#define OFF_W1L (OFF_W + WPL)
#define OFF_W2H (OFF_W + 2 * WPL)
#define OFF_W2L (OFF_W + 3 * WPL)
#define OFF_RED (OFF_W + 4 * WPL)  // 212992
#define OFF_SDOT (OFF_RED)
#define OFF_SN1  (OFF_RED + 1024)
#define OFF_SN2  (OFF_RED + 2048)
#define OFF_P2A  (OFF_RED + 3072)
#define OFF_P2B  (OFF_RED + 3584)
#define SMEM_TOTAL (OFF_RED + 4096)   // 217088

static __device__ __forceinline__ uint32_t s2u(const void* p) {
    uint32_t a;
    asm("{ .reg .u64 t; cvta.to.shared.u64 t, %1; cvt.u32.u64 %0, t; }"
        : "=r"(a) : "l"(p));
    return a;
}

#define LDSM4(R, addr)                                                        \
    asm volatile("ldmatrix.sync.aligned.m8n8.x4.shared.b16 {%0,%1,%2,%3},[%4];" \
                 : "=r"((R)[0]), "=r"((R)[1]), "=r"((R)[2]), "=r"((R)[3])     \
                 : "r"(addr))

#define LDSM4T(R, addr)                                                       \
    asm volatile("ldmatrix.sync.aligned.m8n8.x4.trans.shared.b16 {%0,%1,%2,%3},[%4];" \
                 : "=r"((R)[0]), "=r"((R)[1]), "=r"((R)[2]), "=r"((R)[3])     \
                 : "r"(addr))

#define MMA16816(C, A, B0, B1)                                                \
    asm volatile("mma.sync.aligned.m16n8k16.row.col.f32.bf16.bf16.f32 "       \
                 "{%0,%1,%2,%3},{%4,%5,%6,%7},{%8,%9},{%0,%1,%2,%3};"         \
                 : "+f"((C)[0]), "+f"((C)[1]), "+f"((C)[2]), "+f"((C)[3])     \
                 : "r"((A)[0]), "r"((A)[1]), "r"((A)[2]), "r"((A)[3]),        \
                   "r"(B0), "r"(B1))

static __device__ __forceinline__ uint32_t pack_hi2(float a, float b) {
    __nv_bfloat162 h = __floats2bfloat162_rn(a, b);
    return *reinterpret_cast<uint32_t*>(&h);
}
// split 8 floats (two float4) into hi/lo bf16x8 (uint4 each)
static __device__ __forceinline__ void split8(float4 u, float4 v,
                                              uint4& hi, uint4& lo) {
    hi.x = pack_hi2(u.x, u.y);
    hi.y = pack_hi2(u.z, u.w);
    hi.z = pack_hi2(v.x, v.y);
    hi.w = pack_hi2(v.z, v.w);
    __nv_bfloat162 h;
    float r0, r1;
    h = *reinterpret_cast<__nv_bfloat162*>(&hi.x);
    r0 = u.x - __bfloat162float(h.x); r1 = u.y - __bfloat162float(h.y);
    lo.x = pack_hi2(r0, r1);
    h = *reinterpret_cast<__nv_bfloat162*>(&hi.y);
    r0 = u.z - __bfloat162float(h.x); r1 = u.w - __bfloat162float(h.y);
    lo.y = pack_hi2(r0, r1);
    h = *reinterpret_cast<__nv_bfloat162*>(&hi.z);
    r0 = v.x - __bfloat162float(h.x); r1 = v.y - __bfloat162float(h.y);
    lo.z = pack_hi2(r0, r1);
    h = *reinterpret_cast<__nv_bfloat162*>(&hi.w);
    r0 = v.z - __bfloat162float(h.x); r1 = v.w - __bfloat162float(h.y);
    lo.w = pack_hi2(r0, r1);
}

__global__ __launch_bounds__(256, 1)
void ntn_hmma_kernel(const float* __restrict__ x1g,
                     const float* __restrict__ x2g,
                     const float* __restrict__ W1g,
                     const float* __restrict__ W2g,
                     const float* __restrict__ Vg,
                     const float* __restrict__ bg,
                     float* __restrict__ out) {
    extern __shared__ char smem[];
    const uint32_t sb = s2u(smem);
    const int tid   = threadIdx.x;
    const int lane  = tid & 31;
    const int w     = tid >> 5;
    const int wm    = w & 3;      // M-warp: rows 32*wm
    const int wn    = w >> 2;     // N-warp: e-cols 32*wn within the 64-col e-block
    const int k     = blockIdx.y;
    const int rbase = blockIdx.x * BM;

    float* sdot = (float*)(smem + OFF_SDOT);
    float* sn1  = (float*)(smem + OFF_SN1);
    float* sn2  = (float*)(smem + OFF_SN2);
    float* p2a  = (float*)(smem + OFF_P2A);
    float* p2b  = (float*)(smem + OFF_P2B);

    // ================= prologue: X -> bf16 hi/lo planes + part2 =================
    {
        const int r = tid & 127;
        const bool is2 = tid >= 128;
        const float* xr = (is2 ? x2g : x1g) + (size_t)(rbase + r) * DD;
        const float4* xr4 = (const float4*)xr;
        const float4* vv4 = (const float4*)(Vg + (size_t)k * 2 * DD + (is2 ? DD : 0));
        char* ph = smem + (is2 ? OFF_X2H : OFF_X1H) + r * XROWB;
        char* pl = smem + (is2 ? OFF_X2L : OFF_X1L) + r * XROWB;
        float p2 = 0.f;
        #pragma unroll
        for (int j = 0; j < 16; j++) {
            float4 u = xr4[2 * j], v = xr4[2 * j + 1];
            float4 va = vv4[2 * j], vb = vv4[2 * j + 1];
            p2 = fmaf(u.x, va.x, p2); p2 = fmaf(u.y, va.y, p2);
            p2 = fmaf(u.z, va.z, p2); p2 = fmaf(u.w, va.w, p2);
            p2 = fmaf(v.x, vb.x, p2); p2 = fmaf(v.y, vb.y, p2);
            p2 = fmaf(v.z, vb.z, p2); p2 = fmaf(v.w, vb.w, p2);
            uint4 hi, lo;
            split8(u, v, hi, lo);
            *(uint4*)(ph + j * 16) = hi;
            *(uint4*)(pl + j * 16) = lo;
        }
        if (is2) p2b[r] = p2; else p2a[r] = p2;
    }

    // ldmatrix lane address components
    const int arow  = (lane & 7) + ((lane >> 3) & 1) * 8;  // row within 16 (A) / d within 16 (B)
    const int half8 = (lane >> 4);                         // k-half (A) / e-half (B)
    const uint32_t aoff = (uint32_t)((wm * 32 + arow) * XROWB + half8 * 16);
    const uint32_t boff = (uint32_t)(arow * WROWB + wn * 64 + half8 * 16);
    const uint32_t xh[2] = { sb + OFF_X1H + aoff, sb + OFF_X2H + aoff };
    const uint32_t xl[2] = { sb + OFF_X1L + aoff, sb + OFF_X2L + aoff };
    const uint32_t wh[2] = { sb + OFF_W1H + boff, sb + OFF_W2H + boff };
    const uint32_t wl[2] = { sb + OFF_W1L + boff, sb + OFF_W2L + boff };

    const float* wsrc[2] = { W1g + (size_t)k * DD * DD, W2g + (size_t)k * DD * DD };

    float dv[4]  = {0.f, 0.f, 0.f, 0.f};
    float n1v[4] = {0.f, 0.f, 0.f, 0.f};
    float n2v[4] = {0.f, 0.f, 0.f, 0.f};

    for (int eb = 0; eb < 2; eb++) {
        __syncthreads();   // X planes ready (eb 0) / prior GEMM done (eb 1)
        // ---- convert W e-block: thread -> (matrix, d-row) ----
        {
            const int mat = tid >> 7;
            const int d   = tid & 127;
            const float4* src = (const float4*)(wsrc[mat] + (size_t)d * DD + eb * 64);
            char* dh = smem + (mat ? OFF_W2H : OFF_W1H) + d * WROWB;
            char* dl = smem + (mat ? OFF_W2L : OFF_W1L) + d * WROWB;
            #pragma unroll
            for (int j = 0; j < 8; j++) {
                uint4 hi, lo;
                split8(src[2 * j], src[2 * j + 1], hi, lo);
                *(uint4*)(dh + j * 16) = hi;
                *(uint4*)(dl + j * 16) = lo;
            }
        }
        __syncthreads();

        // ---- GEMM: c1 = X1 @ W1 block, c2 = X2 @ W2 block (split-3 each) ----
        float c1[2][4][4], c2[2][4][4];
        #pragma unroll
        for (int mt = 0; mt < 2; mt++)
            #pragma unroll
            for (int nt = 0; nt < 4; nt++)
                #pragma unroll
                for (int q = 0; q < 4; q++) { c1[mt][nt][q] = 0.f; c2[mt][nt][q] = 0.f; }

        #pragma unroll
        for (int ds = 0; ds < 8; ds++) {
            #pragma unroll
            for (int g = 0; g < 2; g++) {
                uint32_t ah[2][4], al[2][4], bh[2][4], bl[2][4];
                #pragma unroll
                for (int mt = 0; mt < 2; mt++) {
                    const uint32_t ao = (uint32_t)(mt * 16 * XROWB + ds * 32);
                    LDSM4(ah[mt], xh[g] + ao);
                    LDSM4(al[mt], xl[g] + ao);
                }
                #pragma unroll
                for (int pr = 0; pr < 2; pr++) {
                    const uint32_t bo = (uint32_t)(ds * 16 * WROWB + pr * 32);
                    LDSM4T(bh[pr], wh[g] + bo);
                    LDSM4T(bl[pr], wl[g] + bo);
                }
                float (*cc)[4][4] = g ? c2 : c1;
                // product 0: Ah*Bh ; product 1: Ah*Bl ; product 2: Al*Bh
                #pragma unroll
                for (int mt = 0; mt < 2; mt++)
                    #pragma unroll
                    for (int nt = 0; nt < 4; nt++)
                        MMA16816(cc[mt][nt], ah[mt], bh[nt >> 1][(nt & 1) * 2],
                                 bh[nt >> 1][(nt & 1) * 2 + 1]);
                #pragma unroll
                for (int mt = 0; mt < 2; mt++)
                    #pragma unroll
                    for (int nt = 0; nt < 4; nt++)
                        MMA16816(cc[mt][nt], ah[mt], bl[nt >> 1][(nt & 1) * 2],
                                 bl[nt >> 1][(nt & 1) * 2 + 1]);
                #pragma unroll
                for (int mt = 0; mt < 2; mt++)
                    #pragma unroll
                    for (int nt = 0; nt < 4; nt++)
                        MMA16816(cc[mt][nt], al[mt], bh[nt >> 1][(nt & 1) * 2],
                                 bh[nt >> 1][(nt & 1) * 2 + 1]);
            }
        }

        // ---- fold e-block fragment into per-row reductions ----
        #pragma unroll
        for (int mt = 0; mt < 2; mt++)
            #pragma unroll
            for (int nt = 0; nt < 4; nt++) {
                const int s0 = mt * 2;
                float a0 = c1[mt][nt][0], b0 = c2[mt][nt][0];
                float a1 = c1[mt][nt][1], b1 = c2[mt][nt][1];
                float a2 = c1[mt][nt][2], b2 = c2[mt][nt][2];
                float a3 = c1[mt][nt][3], b3 = c2[mt][nt][3];
                dv[s0]      = fmaf(a0, b0, fmaf(a1, b1, dv[s0]));
                n1v[s0]     = fmaf(a0, a0, fmaf(a1, a1, n1v[s0]));
                n2v[s0]     = fmaf(b0, b0, fmaf(b1, b1, n2v[s0]));
                dv[s0 + 1]  = fmaf(a2, b2, fmaf(a3, b3, dv[s0 + 1]));
                n1v[s0 + 1] = fmaf(a2, a2, fmaf(a3, a3, n1v[s0 + 1]));
                n2v[s0 + 1] = fmaf(b2, b2, fmaf(b3, b3, n2v[s0 + 1]));
            }
    }

    // ---- reduce across the 4 lanes sharing a row, stage per-warpN partials ----
    #pragma unroll
    for (int s = 0; s < 4; s++) {
        #pragma unroll
        for (int off = 1; off <= 2; off <<= 1) {
            dv[s]  += __shfl_xor_sync(0xffffffffu, dv[s],  off);
            n1v[s] += __shfl_xor_sync(0xffffffffu, n1v[s], off);
            n2v[s] += __shfl_xor_sync(0xffffffffu, n2v[s], off);
        }
    }
    if ((lane & 3) == 0) {
        #pragma unroll
        for (int s = 0; s < 4; s++) {
            const int row = wm * 32 + (s >> 1) * 16 + (s & 1) * 8 + (lane >> 2);
            sdot[wn * 128 + row] = dv[s];
            sn1[wn * 128 + row]  = n1v[s];
            sn2[wn * 128 + row]  = n2v[s];
        }
    }
    __syncthreads();

    // ---- epilogue: combine, cosine + part2 + bias, relu, store ----
    if (tid < 128) {
        const int row = tid;
        float dot = sdot[row] + sdot[128 + row];
        float nn1 = sn1[row]  + sn1[128 + row];
        float nn2 = sn2[row]  + sn2[128 + row];
        float s1 = fmaxf(sqrtf(nn1), EPSN);
        float s2 = fmaxf(sqrtf(nn2), EPSN);
        float v = dot / (s1 * s2) + p2a[row] + p2b[row] + bg[k];
        out[(size_t)(rbase + row) * KK + k] = fmaxf(v, 0.f);
    }
}

extern "C" void kernel_launch(void* const* d_in, const int* in_sizes, int n_in,
                              void* d_out, int out_size) {
    const float* x1 = (const float*)d_in[0];
    const float* x2 = (const float*)d_in[1];
    const float* W1 = (const float*)d_in[2];
    const float* W2 = (const float*)d_in[3];
    const float* V  = (const float*)d_in[4];
    const float* b  = (const float*)d_in[5];
    float* out = (float*)d_out;

    cudaFuncSetAttribute(ntn_hmma_kernel,
                         cudaFuncAttributeMaxDynamicSharedMemorySize, SMEM_TOTAL);
    dim3 grid(NN / BM, KK);
    ntn_hmma_kernel<<<grid, 256, SMEM_TOTAL>>>(x1, x2, W1, W2, V, b, out);
}

// round 5
// speedup vs baseline: 3.5358x; 2.0927x over previous
#include <cuda_runtime.h>
#include <cuda_bf16.h>
#include <cstdint>

// NTN: out[n,k] = relu( cos(x1@W1[k], x2@W2[k]) + [x1,x2]@V[k] + b[k] )
// R5: precomputed bf16 hi/lo operands; A fragment-major from global (L2),
// B via cp.async + ldmatrix; 16-warp main kernel, split-3 HMMA, fp32 epilogue.

#define NN 32768
#define DD 128
#define KK 32
#define EPSN 1e-8f

// ---------------- global scratch (allowed: __device__ arrays) ----------------
__device__ uint4 gXfrag[2][2][2048][8][32];   // [mat][plane][rowtile16][dtile16][lane] : 33.5MB
__device__ uint4 gWq[32][4][2][128][8];       // [k][mat*2+plane][ehalf][d][e8granule] : 4MB
__device__ float gP2[(size_t)NN * KK];        // part2 + bias : 4MB

// ---------------- helpers ----------------
static __device__ __forceinline__ uint32_t s2u(const void* p) {
    uint32_t a;
    asm("{ .reg .u64 t; cvta.to.shared.u64 t, %1; cvt.u32.u64 %0, t; }"
        : "=r"(a) : "l"(p));
    return a;
}
static __device__ __forceinline__ uint32_t pack2(float a, float b) {
    __nv_bfloat162 h = __floats2bfloat162_rn(a, b);
    return *reinterpret_cast<uint32_t*>(&h);
}
static __device__ __forceinline__ void split2(float a, float b,
                                              uint32_t& hi, uint32_t& lo) {
    __nv_bfloat162 h = __floats2bfloat162_rn(a, b);
    float ra = a - __bfloat162float(h.x);
    float rb = b - __bfloat162float(h.y);
    hi = *reinterpret_cast<uint32_t*>(&h);
    lo = pack2(ra, rb);
}

#define LDSM4T(R, addr)                                                         \
    asm volatile("ldmatrix.sync.aligned.m8n8.x4.trans.shared.b16 {%0,%1,%2,%3},[%4];" \
                 : "=r"((R)[0]), "=r"((R)[1]), "=r"((R)[2]), "=r"((R)[3])       \
                 : "r"(addr))

#define MMA16816(C, A, B0, B1)                                                  \
    asm volatile("mma.sync.aligned.m16n8k16.row.col.f32.bf16.bf16.f32 "         \
                 "{%0,%1,%2,%3},{%4,%5,%6,%7},{%8,%9},{%0,%1,%2,%3};"           \
                 : "+f"((C)[0]), "+f"((C)[1]), "+f"((C)[2]), "+f"((C)[3])       \
                 : "r"((A)[0]), "r"((A)[1]), "r"((A)[2]), "r"((A)[3]),          \
                   "r"(B0), "r"(B1))

static __device__ __forceinline__ void cp16(uint32_t dst, const void* src) {
    asm volatile("cp.async.cg.shared.global [%0], [%1], 16;"
                 :: "r"(dst), "l"(src) : "memory");
}
static __device__ __forceinline__ void cp_commit() {
    asm volatile("cp.async.commit_group;" ::: "memory");
}
template <int N>
static __device__ __forceinline__ void cp_wait() {
    asm volatile("cp.async.wait_group %0;" :: "n"(N) : "memory");
}

// ---------------- prep kernels ----------------
// X -> bf16 hi/lo in mma m16n8k16 A-fragment-major order.
__global__ __launch_bounds__(256) void prep_x(const float* __restrict__ x1,
                                              const float* __restrict__ x2) {
    int gw   = (blockIdx.x * 256 + threadIdx.x) >> 5;   // 0..32767
    int lane = threadIdx.x & 31;
    int dt = gw & 7;
    int rt = (gw >> 3) & 2047;
    int m  = gw >> 14;
    const float* x = m ? x2 : x1;
    int r = rt * 16 + (lane >> 2);
    int c = dt * 16 + (lane & 3) * 2;
    const float* p0 = x + (size_t)r * DD + c;
    float2 v00 = *(const float2*)(p0);
    float2 v01 = *(const float2*)(p0 + 8);
    float2 v10 = *(const float2*)(p0 + 8 * DD);
    float2 v11 = *(const float2*)(p0 + 8 * DD + 8);
    uint4 hi, lo;
    split2(v00.x, v00.y, hi.x, lo.x);   // a0: (r,   c..c+1)
    split2(v10.x, v10.y, hi.y, lo.y);   // a1: (r+8, c..c+1)
    split2(v01.x, v01.y, hi.z, lo.z);   // a2: (r,   c+8..c+9)
    split2(v11.x, v11.y, hi.w, lo.w);   // a3: (r+8, c+8..c+9)
    gXfrag[m][0][rt][dt][lane] = hi;
    gXfrag[m][1][rt][dt][lane] = lo;
}

// W -> bf16 hi/lo [d][e] planes per (k, e-half), 16B granules.
__global__ __launch_bounds__(256) void prep_w(const float* __restrict__ W1,
                                              const float* __restrict__ W2) {
    int t  = blockIdx.x * 256 + threadIdx.x;   // 0..131071
    int e8 = t & 7;
    int d  = (t >> 3) & 127;
    int eb = (t >> 10) & 1;
    int m  = (t >> 11) & 1;
    int k  = t >> 12;
    const float* w = (m ? W2 : W1) + (size_t)k * DD * DD + (size_t)d * DD
                   + eb * 64 + e8 * 8;
    float4 u = *(const float4*)(w);
    float4 v = *(const float4*)(w + 4);
    uint4 hi, lo;
    split2(u.x, u.y, hi.x, lo.x);
    split2(u.z, u.w, hi.y, lo.y);
    split2(v.x, v.y, hi.z, lo.z);
    split2(v.z, v.w, hi.w, lo.w);
    gWq[k][m * 2 + 0][eb][d][e8] = hi;
    gWq[k][m * 2 + 1][eb][d][e8] = lo;
}

// part2 + bias, exact fp32.
__global__ __launch_bounds__(256) void prep_p2(const float* __restrict__ x1,
                                               const float* __restrict__ x2,
                                               const float* __restrict__ Vg,
                                               const float* __restrict__ bg) {
    __shared__ float Vs[KK * 256];
    __shared__ float bs[KK];
    int tid = threadIdx.x;
    for (int i = tid; i < KK * 256; i += 256) Vs[i] = Vg[i];
    if (tid < KK) bs[tid] = bg[tid];
    __syncthreads();
    int n = blockIdx.x * 256 + tid;
    float acc[KK];
    #pragma unroll
    for (int k = 0; k < KK; k++) acc[k] = bs[k];
    const float4* xa = (const float4*)(x1 + (size_t)n * DD);
    const float4* xb = (const float4*)(x2 + (size_t)n * DD);
    #pragma unroll 4
    for (int f = 0; f < 32; f++) {
        float4 xv = xa[f];
        #pragma unroll
        for (int k = 0; k < KK; k++) {
            float4 vv = *(const float4*)(&Vs[k * 256 + f * 4]);
            acc[k] = fmaf(xv.x, vv.x, fmaf(xv.y, vv.y,
                     fmaf(xv.z, vv.z, fmaf(xv.w, vv.w, acc[k]))));
        }
    }
    #pragma unroll 4
    for (int f = 0; f < 32; f++) {
        float4 xv = xb[f];
        #pragma unroll
        for (int k = 0; k < KK; k++) {
            float4 vv = *(const float4*)(&Vs[k * 256 + 128 + f * 4]);
            acc[k] = fmaf(xv.x, vv.x, fmaf(xv.y, vv.y,
                     fmaf(xv.z, vv.z, fmaf(xv.w, vv.w, acc[k]))));
        }
    }
    #pragma unroll
    for (int k = 0; k < KK; k++) gP2[(size_t)n * KK + k] = acc[k];
}

// ---------------- main kernel ----------------
#define WROWB 144                 // smem W row pitch (bytes), conflict-free ldmatrix
#define WPL   (128 * WROWB)       // one plane: 18432
#define WBUF  (4 * WPL)           // 4 planes (W1h,W1l,W2h,W2l): 73728
#define OFF_RED (2 * WBUF)        // 147456
#define SMEM_MAIN (OFF_RED + 6144)

__global__ __launch_bounds__(512, 1)
void ntn_main(float* __restrict__ out) {
    extern __shared__ char smem[];
    const uint32_t sb = s2u(smem);
    const int tid  = threadIdx.x;
    const int lane = tid & 31;
    const int w    = tid >> 5;
    const int wm   = w & 7;       // row-warp: rows 32*wm .. 32*wm+31 (of 256)
    const int wn   = w >> 3;      // col-warp: cols 32*wn within 64-col e-half
    const int k     = blockIdx.y;
    const int rbase = blockIdx.x * 256;
    const int rtb   = blockIdx.x * 16 + wm * 2;

    float* sdot = (float*)(smem + OFF_RED);
    float* sn1  = sdot + 512;
    float* sn2  = sn1 + 512;

    // ---- cp.async both W e-halves (double-buffered) ----
    #pragma unroll
    for (int eb = 0; eb < 2; eb++) {
        #pragma unroll
        for (int i = 0; i < 8; i++) {
            int idx = tid + 512 * i;            // 0..4095
            int mp  = idx >> 10;
            int d   = (idx >> 3) & 127;
            int e8  = idx & 7;
            cp16(sb + eb * WBUF + mp * WPL + d * WROWB + e8 * 16,
                 &gWq[k][mp][eb][d][e8]);
        }
        cp_commit();
    }

    const int arow  = (lane & 7) + ((lane >> 3) & 1) * 8;
    const int half8 = lane >> 4;
    const uint32_t boff = (uint32_t)(arow * WROWB + wn * 64 + half8 * 16);

    float dv[4]  = {0.f, 0.f, 0.f, 0.f};
    float n1v[4] = {0.f, 0.f, 0.f, 0.f};
    float n2v[4] = {0.f, 0.f, 0.f, 0.f};

    cp_wait<1>();
    __syncthreads();

    #pragma unroll
    for (int eb = 0; eb < 2; eb++) {
        if (eb == 1) { cp_wait<0>(); __syncthreads(); }

        float c1[2][4][4], c2[2][4][4];
        #pragma unroll
        for (int mt = 0; mt < 2; mt++)
            #pragma unroll
            for (int nt = 0; nt < 4; nt++)
                #pragma unroll
                for (int q = 0; q < 4; q++) { c1[mt][nt][q] = 0.f; c2[mt][nt][q] = 0.f; }

        #pragma unroll
        for (int ds = 0; ds < 8; ds++) {
            #pragma unroll
            for (int g = 0; g < 2; g++) {
                uint4 ah[2], al[2];
                ah[0] = gXfrag[g][0][rtb]     [ds][lane];
                ah[1] = gXfrag[g][0][rtb + 1] [ds][lane];
                al[0] = gXfrag[g][1][rtb]     [ds][lane];
                al[1] = gXfrag[g][1][rtb + 1] [ds][lane];

                uint32_t bh[2][4], bl[2][4];
                const uint32_t wbase = sb + eb * WBUF + (g * 2) * WPL + boff
                                     + (uint32_t)(ds * 16 * WROWB);
                #pragma unroll
                for (int pr = 0; pr < 2; pr++) {
                    LDSM4T(bh[pr], wbase + pr * 32);
                    LDSM4T(bl[pr], wbase + WPL + pr * 32);
                }

                float (*cc)[4][4] = g ? c2 : c1;
                // product 0: Ah*Bh
                #pragma unroll
                for (int mt = 0; mt < 2; mt++)
                    #pragma unroll
                    for (int nt = 0; nt < 4; nt++)
                        MMA16816(cc[mt][nt], ((const uint32_t*)&ah[mt]),
                                 bh[nt >> 1][(nt & 1) * 2], bh[nt >> 1][(nt & 1) * 2 + 1]);
                // product 1: Ah*Bl
                #pragma unroll
                for (int mt = 0; mt < 2; mt++)
                    #pragma unroll
                    for (int nt = 0; nt < 4; nt++)
                        MMA16816(cc[mt][nt], ((const uint32_t*)&ah[mt]),
                                 bl[nt >> 1][(nt & 1) * 2], bl[nt >> 1][(nt & 1) * 2 + 1]);
                // product 2: Al*Bh
                #pragma unroll
                for (int mt = 0; mt < 2; mt++)
                    #pragma unroll
                    for (int nt = 0; nt < 4; nt++)
                        MMA16816(cc[mt][nt], ((const uint32_t*)&al[mt]),
                                 bh[nt >> 1][(nt & 1) * 2], bh[nt >> 1][(nt & 1) * 2 + 1]);
            }
        }

        // fold e-half fragment into per-row reductions
        #pragma unroll
        for (int mt = 0; mt < 2; mt++)
            #pragma unroll
            for (int nt = 0; nt < 4; nt++) {
                const int s0 = mt * 2;
                float a0 = c1[mt][nt][0], b0 = c2[mt][nt][0];
                float a1 = c1[mt][nt][1], b1 = c2[mt][nt][1];
                float a2 = c1[mt][nt][2], b2 = c2[mt][nt][2];
                float a3 = c1[mt][nt][3], b3 = c2[mt][nt][3];
                dv[s0]      = fmaf(a0, b0, fmaf(a1, b1, dv[s0]));
                n1v[s0]     = fmaf(a0, a0, fmaf(a1, a1, n1v[s0]));
                n2v[s0]     = fmaf(b0, b0, fmaf(b1, b1, n2v[s0]));
                dv[s0 + 1]  = fmaf(a2, b2, fmaf(a3, b3, dv[s0 + 1]));
                n1v[s0 + 1] = fmaf(a2, a2, fmaf(a3, a3, n1v[s0 + 1]));
                n2v[s0 + 1] = fmaf(b2, b2, fmaf(b3, b3, n2v[s0 + 1]));
            }
    }

    // ---- lane reduce (4 lanes share a row) + stage per-wn partials ----
    #pragma unroll
    for (int s = 0; s < 4; s++) {
        #pragma unroll
        for (int off = 1; off <= 2; off <<= 1) {
            dv[s]  += __shfl_xor_sync(0xffffffffu, dv[s],  off);
            n1v[s] += __shfl_xor_sync(0xffffffffu, n1v[s], off);
            n2v[s] += __shfl_xor_sync(0xffffffffu, n2v[s], off);
        }
    }
    if ((lane & 3) == 0) {
        #pragma unroll
        for (int s = 0; s < 4; s++) {
            const int row = wm * 32 + (s >> 1) * 16 + (s & 1) * 8 + (lane >> 2);
            sdot[wn * 256 + row] = dv[s];
            sn1[wn * 256 + row]  = n1v[s];
            sn2[wn * 256 + row]  = n2v[s];
        }
    }
    __syncthreads();

    // ---- epilogue ----
    if (tid < 256) {
        const int row = tid;
        float dot = sdot[row] + sdot[256 + row];
        float nn1 = sn1[row]  + sn1[256 + row];
        float nn2 = sn2[row]  + sn2[256 + row];
        float s1 = fmaxf(sqrtf(nn1), EPSN);
        float s2 = fmaxf(sqrtf(nn2), EPSN);
        float v = dot / (s1 * s2) + gP2[(size_t)(rbase + row) * KK + k];
        out[(size_t)(rbase + row) * KK + k] = fmaxf(v, 0.f);
    }
}

extern "C" void kernel_launch(void* const* d_in, const int* in_sizes, int n_in,
                              void* d_out, int out_size) {
    const float* x1 = (const float*)d_in[0];
    const float* x2 = (const float*)d_in[1];
    const float* W1 = (const float*)d_in[2];
    const float* W2 = (const float*)d_in[3];
    const float* V  = (const float*)d_in[4];
    const float* b  = (const float*)d_in[5];
    float* out = (float*)d_out;

    prep_x<<<4096, 256>>>(x1, x2);
    prep_w<<<512, 256>>>(W1, W2);
    prep_p2<<<NN / 256, 256>>>(x1, x2, V, b);

    cudaFuncSetAttribute(ntn_main,
                         cudaFuncAttributeMaxDynamicSharedMemorySize, SMEM_MAIN);
    dim3 grid(NN / 256, KK);
    ntn_main<<<grid, 512, SMEM_MAIN>>>(out);
}

// round 6
// speedup vs baseline: 3.7756x; 1.0678x over previous
#include <cuda_runtime.h>
#include <cuda_bf16.h>
#include <cstdint>

// NTN: out[n,k] = relu( cos(x1@W1[k], x2@W2[k]) + [x1,x2]@V[k] + b[k] )
// R6: split-3 bf16 HMMA; 256-thread CTAs, 2 CTAs/SM, single-buffered W smem,
// explicit A-fragment register double-buffer, per-e-half smem fold.

#define NN 32768
#define DD 128
#define KK 32
#define EPSN 1e-8f

// ---------------- global scratch ----------------
__device__ uint4 gXfrag[2][2][2048][8][32];   // [mat][plane][rowtile16][dtile16][lane]
__device__ uint4 gWq[32][4][2][128][8];       // [k][mat*2+plane][ehalf][d][e8]
__device__ float gP2[(size_t)NN * KK];        // part2 + bias

// ---------------- helpers ----------------
static __device__ __forceinline__ uint32_t s2u(const void* p) {
    uint32_t a;
    asm("{ .reg .u64 t; cvta.to.shared.u64 t, %1; cvt.u32.u64 %0, t; }"
        : "=r"(a) : "l"(p));
    return a;
}
static __device__ __forceinline__ uint32_t pack2(float a, float b) {
    __nv_bfloat162 h = __floats2bfloat162_rn(a, b);
    return *reinterpret_cast<uint32_t*>(&h);
}
static __device__ __forceinline__ void split2(float a, float b,
                                              uint32_t& hi, uint32_t& lo) {
    __nv_bfloat162 h = __floats2bfloat162_rn(a, b);
    float ra = a - __bfloat162float(h.x);
    float rb = b - __bfloat162float(h.y);
    hi = *reinterpret_cast<uint32_t*>(&h);
    lo = pack2(ra, rb);
}

#define LDSM4T(R, addr)                                                         \
    asm volatile("ldmatrix.sync.aligned.m8n8.x4.trans.shared.b16 {%0,%1,%2,%3},[%4];" \
                 : "=r"((R)[0]), "=r"((R)[1]), "=r"((R)[2]), "=r"((R)[3])       \
                 : "r"(addr))

#define MMA16816(C, A, B0, B1)                                                  \
    asm volatile("mma.sync.aligned.m16n8k16.row.col.f32.bf16.bf16.f32 "         \
                 "{%0,%1,%2,%3},{%4,%5,%6,%7},{%8,%9},{%0,%1,%2,%3};"           \
                 : "+f"((C)[0]), "+f"((C)[1]), "+f"((C)[2]), "+f"((C)[3])       \
                 : "r"((A)[0]), "r"((A)[1]), "r"((A)[2]), "r"((A)[3]),          \
                   "r"(B0), "r"(B1))

static __device__ __forceinline__ void cp16(uint32_t dst, const void* src) {
    asm volatile("cp.async.cg.shared.global [%0], [%1], 16;"
                 :: "r"(dst), "l"(src) : "memory");
}
static __device__ __forceinline__ void cp_commit() {
    asm volatile("cp.async.commit_group;" ::: "memory");
}
template <int N>
static __device__ __forceinline__ void cp_wait() {
    asm volatile("cp.async.wait_group %0;" :: "n"(N) : "memory");
}

// ---------------- prep kernels (unchanged math from R5) ----------------
__global__ __launch_bounds__(256) void prep_x(const float* __restrict__ x1,
                                              const float* __restrict__ x2) {
    int gw   = (blockIdx.x * 256 + threadIdx.x) >> 5;
    int lane = threadIdx.x & 31;
    int dt = gw & 7;
    int rt = (gw >> 3) & 2047;
    int m  = gw >> 14;
    const float* x = m ? x2 : x1;
    int r = rt * 16 + (lane >> 2);
    int c = dt * 16 + (lane & 3) * 2;
    const float* p0 = x + (size_t)r * DD + c;
    float2 v00 = *(const float2*)(p0);
    float2 v01 = *(const float2*)(p0 + 8);
    float2 v10 = *(const float2*)(p0 + 8 * DD);
    float2 v11 = *(const float2*)(p0 + 8 * DD + 8);
    uint4 hi, lo;
    split2(v00.x, v00.y, hi.x, lo.x);
    split2(v10.x, v10.y, hi.y, lo.y);
    split2(v01.x, v01.y, hi.z, lo.z);
    split2(v11.x, v11.y, hi.w, lo.w);
    gXfrag[m][0][rt][dt][lane] = hi;
    gXfrag[m][1][rt][dt][lane] = lo;
}

__global__ __launch_bounds__(256) void prep_w(const float* __restrict__ W1,
                                              const float* __restrict__ W2) {
    int t  = blockIdx.x * 256 + threadIdx.x;
    int e8 = t & 7;
    int d  = (t >> 3) & 127;
    int eb = (t >> 10) & 1;
    int m  = (t >> 11) & 1;
    int k  = t >> 12;
    const float* w = (m ? W2 : W1) + (size_t)k * DD * DD + (size_t)d * DD
                   + eb * 64 + e8 * 8;
    float4 u = *(const float4*)(w);
    float4 v = *(const float4*)(w + 4);
    uint4 hi, lo;
    split2(u.x, u.y, hi.x, lo.x);
    split2(u.z, u.w, hi.y, lo.y);
    split2(v.x, v.y, hi.z, lo.z);
    split2(v.z, v.w, hi.w, lo.w);
    gWq[k][m * 2 + 0][eb][d][e8] = hi;
    gWq[k][m * 2 + 1][eb][d][e8] = lo;
}

__global__ __launch_bounds__(256) void prep_p2(const float* __restrict__ x1,
                                               const float* __restrict__ x2,
                                               const float* __restrict__ Vg,
                                               const float* __restrict__ bg) {
    __shared__ float Vs[KK * 256];
    __shared__ float bs[KK];
    int tid = threadIdx.x;
    for (int i = tid; i < KK * 256; i += 256) Vs[i] = Vg[i];
    if (tid < KK) bs[tid] = bg[tid];
    __syncthreads();
    int n = blockIdx.x * 256 + tid;
    float acc[KK];
    #pragma unroll
    for (int k = 0; k < KK; k++) acc[k] = bs[k];
    const float4* xa = (const float4*)(x1 + (size_t)n * DD);
    const float4* xb = (const float4*)(x2 + (size_t)n * DD);
    #pragma unroll 4
    for (int f = 0; f < 32; f++) {
        float4 xv = xa[f];
        #pragma unroll
        for (int k = 0; k < KK; k++) {
            float4 vv = *(const float4*)(&Vs[k * 256 + f * 4]);
            acc[k] = fmaf(xv.x, vv.x, fmaf(xv.y, vv.y,
                     fmaf(xv.z, vv.z, fmaf(xv.w, vv.w, acc[k]))));
        }
    }
    #pragma unroll 4
    for (int f = 0; f < 32; f++) {
        float4 xv = xb[f];
        #pragma unroll
        for (int k = 0; k < KK; k++) {
            float4 vv = *(const float4*)(&Vs[k * 256 + 128 + f * 4]);
            acc[k] = fmaf(xv.x, vv.x, fmaf(xv.y, vv.y,
                     fmaf(xv.z, vv.z, fmaf(xv.w, vv.w, acc[k]))));
        }
    }
    #pragma unroll
    for (int k = 0; k < KK; k++) gP2[(size_t)n * KK + k] = acc[k];
}

// ---------------- main kernel ----------------
#define WROWB 144
#define WPL   (128 * WROWB)          // 18432
#define WBUF  (4 * WPL)              // 73728 (single e-half, 4 planes)
#define OFF_RED WBUF                 // 3KB reduction area
#define SMEM_MAIN (WBUF + 3072)

__global__ __launch_bounds__(256, 2)
void ntn_main(float* __restrict__ out) {
    extern __shared__ char smem[];
    const uint32_t sb = s2u(smem);
    const int tid  = threadIdx.x;
    const int lane = tid & 31;
    const int w    = tid >> 5;
    const int wm   = w & 3;        // rows 32*wm .. 32*wm+31 (of 128)
    const int wn   = w >> 2;       // 32-col half within the 64-col e-half
    const int k     = blockIdx.y;
    const int rbase = blockIdx.x * 128;
    const int rtb   = blockIdx.x * 8 + wm * 2;

    float* sdot = (float*)(smem + OFF_RED);          // [2][128]
    float* sn1  = sdot + 256;
    float* sn2  = sn1 + 256;

    // ---- cp.async W e-half 0 ----
    #pragma unroll
    for (int i = 0; i < 16; i++) {
        int idx = tid + 256 * i;            // 0..4095
        int mp  = idx >> 10;
        int d   = (idx >> 3) & 127;
        int e8  = idx & 7;
        cp16(sb + mp * WPL + d * WROWB + e8 * 16, &gWq[k][mp][0][d][e8]);
    }
    cp_commit();

    const int arow  = (lane & 7) + ((lane >> 3) & 1) * 8;
    const int half8 = lane >> 4;
    const uint32_t boff = (uint32_t)(arow * WROWB + wn * 64 + half8 * 16);

    // ---- prefetch A step 0 into buffer 0 ----
    uint4 ah[2][2], al[2][2];
    ah[0][0] = gXfrag[0][0][rtb][0][lane];
    ah[0][1] = gXfrag[0][0][rtb + 1][0][lane];
    al[0][0] = gXfrag[0][1][rtb][0][lane];
    al[0][1] = gXfrag[0][1][rtb + 1][0][lane];

    cp_wait<0>();
    __syncthreads();

    #pragma unroll
    for (int eb = 0; eb < 2; eb++) {
        float c1[2][4][4], c2[2][4][4];
        #pragma unroll
        for (int mt = 0; mt < 2; mt++)
            #pragma unroll
            for (int nt = 0; nt < 4; nt++)
                #pragma unroll
                for (int q = 0; q < 4; q++) { c1[mt][nt][q] = 0.f; c2[mt][nt][q] = 0.f; }

        #pragma unroll
        for (int step = 0; step < 16; step++) {
            const int cur = step & 1, nxt = cur ^ 1;
            const int ds = step >> 1, g = step & 1;
            // prefetch next step's A (wraps to step 0; A identical across eb)
            {
                const int ns = (step + 1) & 15;
                const int nds = ns >> 1, ng = ns & 1;
                ah[nxt][0] = gXfrag[ng][0][rtb][nds][lane];
                ah[nxt][1] = gXfrag[ng][0][rtb + 1][nds][lane];
                al[nxt][0] = gXfrag[ng][1][rtb][nds][lane];
                al[nxt][1] = gXfrag[ng][1][rtb + 1][nds][lane];
            }
            // B fragments for (ds, g)
            uint32_t bh[2][4], bl[2][4];
            const uint32_t wbase = sb + (g * 2) * WPL + boff
                                 + (uint32_t)(ds * 16 * WROWB);
            #pragma unroll
            for (int pr = 0; pr < 2; pr++) {
                LDSM4T(bh[pr], wbase + pr * 32);
                LDSM4T(bl[pr], wbase + WPL + pr * 32);
            }
            float (*cc)[4][4] = g ? c2 : c1;
            const uint32_t* Ah0 = (const uint32_t*)&ah[cur][0];
            const uint32_t* Ah1 = (const uint32_t*)&ah[cur][1];
            const uint32_t* Al0 = (const uint32_t*)&al[cur][0];
            const uint32_t* Al1 = (const uint32_t*)&al[cur][1];
            // product 0: Ah*Bh
            #pragma unroll
            for (int nt = 0; nt < 4; nt++) {
                MMA16816(cc[0][nt], Ah0, bh[nt >> 1][(nt & 1) * 2], bh[nt >> 1][(nt & 1) * 2 + 1]);
                MMA16816(cc[1][nt], Ah1, bh[nt >> 1][(nt & 1) * 2], bh[nt >> 1][(nt & 1) * 2 + 1]);
            }
            // product 1: Ah*Bl
            #pragma unroll
            for (int nt = 0; nt < 4; nt++) {
                MMA16816(cc[0][nt], Ah0, bl[nt >> 1][(nt & 1) * 2], bl[nt >> 1][(nt & 1) * 2 + 1]);
                MMA16816(cc[1][nt], Ah1, bl[nt >> 1][(nt & 1) * 2], bl[nt >> 1][(nt & 1) * 2 + 1]);
            }
            // product 2: Al*Bh
            #pragma unroll
            for (int nt = 0; nt < 4; nt++) {
                MMA16816(cc[0][nt], Al0, bh[nt >> 1][(nt & 1) * 2], bh[nt >> 1][(nt & 1) * 2 + 1]);
                MMA16816(cc[1][nt], Al1, bh[nt >> 1][(nt & 1) * 2], bh[nt >> 1][(nt & 1) * 2 + 1]);
            }
        }

        if (eb == 0) {
            __syncthreads();            // all warps done reading W e-half 0
            #pragma unroll
            for (int i = 0; i < 16; i++) {
                int idx = tid + 256 * i;
                int mp  = idx >> 10;
                int d   = (idx >> 3) & 127;
                int e8  = idx & 7;
                cp16(sb + mp * WPL + d * WROWB + e8 * 16, &gWq[k][mp][1][d][e8]);
            }
            cp_commit();
        }

        // ---- fold this e-half into per-row partials (overlaps cp.async) ----
        float dvt[4], n1t[4], n2t[4];
        #pragma unroll
        for (int s = 0; s < 4; s++) { dvt[s] = 0.f; n1t[s] = 0.f; n2t[s] = 0.f; }
        #pragma unroll
        for (int mt = 0; mt < 2; mt++)
            #pragma unroll
            for (int nt = 0; nt < 4; nt++) {
                const int s0 = mt * 2;
                float a0 = c1[mt][nt][0], b0 = c2[mt][nt][0];
                float a1 = c1[mt][nt][1], b1 = c2[mt][nt][1];
                float a2 = c1[mt][nt][2], b2 = c2[mt][nt][2];
                float a3 = c1[mt][nt][3], b3 = c2[mt][nt][3];
                dvt[s0]      = fmaf(a0, b0, fmaf(a1, b1, dvt[s0]));
                n1t[s0]      = fmaf(a0, a0, fmaf(a1, a1, n1t[s0]));
                n2t[s0]      = fmaf(b0, b0, fmaf(b1, b1, n2t[s0]));
                dvt[s0 + 1]  = fmaf(a2, b2, fmaf(a3, b3, dvt[s0 + 1]));
                n1t[s0 + 1]  = fmaf(a2, a2, fmaf(a3, a3, n1t[s0 + 1]));
                n2t[s0 + 1]  = fmaf(b2, b2, fmaf(b3, b3, n2t[s0 + 1]));
            }
        #pragma unroll
        for (int s = 0; s < 4; s++) {
            #pragma unroll
            for (int off = 1; off <= 2; off <<= 1) {
                dvt[s] += __shfl_xor_sync(0xffffffffu, dvt[s], off);
                n1t[s] += __shfl_xor_sync(0xffffffffu, n1t[s], off);
                n2t[s] += __shfl_xor_sync(0xffffffffu, n2t[s], off);
            }
        }
        if ((lane & 3) == 0) {
            #pragma unroll
            for (int s = 0; s < 4; s++) {
                const int row = wm * 32 + (s >> 1) * 16 + (s & 1) * 8 + (lane >> 2);
                const int idx = wn * 128 + row;
                if (eb == 0) {
                    sdot[idx] = dvt[s]; sn1[idx] = n1t[s]; sn2[idx] = n2t[s];
                } else {
                    sdot[idx] += dvt[s]; sn1[idx] += n1t[s]; sn2[idx] += n2t[s];
                }
            }
        }

        if (eb == 0) { cp_wait<0>(); __syncthreads(); }
    }

    __syncthreads();

    // ---- epilogue ----
    if (tid < 128) {
        const int row = tid;
        float dot = sdot[row] + sdot[128 + row];
        float nn1 = sn1[row]  + sn1[128 + row];
        float nn2 = sn2[row]  + sn2[128 + row];
        float s1 = fmaxf(sqrtf(nn1), EPSN);
        float s2 = fmaxf(sqrtf(nn2), EPSN);
        float v = dot / (s1 * s2) + gP2[(size_t)(rbase + row) * KK + k];
        out[(size_t)(rbase + row) * KK + k] = fmaxf(v, 0.f);
    }
}

extern "C" void kernel_launch(void* const* d_in, const int* in_sizes, int n_in,
                              void* d_out, int out_size) {
    const float* x1 = (const float*)d_in[0];
    const float* x2 = (const float*)d_in[1];
    const float* W1 = (const float*)d_in[2];
    const float* W2 = (const float*)d_in[3];
    const float* V  = (const float*)d_in[4];
    const float* b  = (const float*)d_in[5];
    float* out = (float*)d_out;

    prep_x<<<4096, 256>>>(x1, x2);
    prep_w<<<512, 256>>>(W1, W2);
    prep_p2<<<NN / 256, 256>>>(x1, x2, V, b);

    cudaFuncSetAttribute(ntn_main,
                         cudaFuncAttributeMaxDynamicSharedMemorySize, SMEM_MAIN);
    dim3 grid(NN / 128, KK);
    ntn_main<<<grid, 256, SMEM_MAIN>>>(out);
}